// round 4
// baseline (speedup 1.0000x reference)
#include <cuda_runtime.h>
#include <math.h>

// Problem constants (shapes fixed for this problem instance)
#define NMAX   50000
#define EMAX   800000
#define F_IN   512
#define H1     256
#define H2     16
#define F_OUT  40

// Scratch: static device arrays referenced directly from kernels.
__device__ float g_h1[NMAX * H1];   // x @ W1
__device__ float g_a1[NMAX * H1];   // aggregated layer1 (relu'd in place)
__device__ float g_h2[NMAX * H2];   // r1 @ W2
__device__ float g_a2[NMAX * H2];   // aggregated layer2 (relu'd in place)
__device__ float g_a3[NMAX * H2];   // aggregated r2 (layer3, aggregate-first)
__device__ int   g_deg[NMAX];
__device__ float g_dinv[NMAX];

// ---------------------------------------------------------------------------
// degree / normalization  (edge_index delivered as int32: [src[E], dst[E]])
// ---------------------------------------------------------------------------
__global__ void zero_deg_kernel(int N) {
    int i = blockIdx.x * blockDim.x + threadIdx.x;
    if (i < N) g_deg[i] = 0;
}

__global__ void count_deg_kernel(const int* __restrict__ ei, int E, int N) {
    int e = blockIdx.x * blockDim.x + threadIdx.x;
    if (e < E) {
        int d = ei[E + e];   // dst
        if (d >= 0 && d < N) atomicAdd(&g_deg[d], 1);
    }
}

__global__ void dinv_kernel(int N) {
    int i = blockIdx.x * blockDim.x + threadIdx.x;
    if (i < N) {
        // +1 for the self-loop appended per node
        g_dinv[i] = rsqrtf((float)(g_deg[i] + 1));
    }
}

// ---------------------------------------------------------------------------
// GEMM1: g_h1[N,256] = A[N,512] @ B[512,256]  register tiled fp32
// ---------------------------------------------------------------------------
#define BM 128
#define BN 64
#define BK 16
#define TM 8
#define TN 4
// threads = (BM/TM)*(BN/TN) = 16*16 = 256

__global__ void gemm1_kernel(const float* __restrict__ A,
                             const float* __restrict__ B, int N) {
    const int K = F_IN, M = H1;
    __shared__ float As[BK][BM + 4];
    __shared__ float Bs[BK][BN];

    int block_row = blockIdx.y * BM;
    int block_col = blockIdx.x * BN;
    int tid = threadIdx.x;
    int tr = tid / (BN / TN);   // 0..15
    int tc = tid % (BN / TN);   // 0..15

    float acc[TM][TN];
#pragma unroll
    for (int i = 0; i < TM; i++)
#pragma unroll
        for (int j = 0; j < TN; j++) acc[i][j] = 0.f;

    for (int k0 = 0; k0 < K; k0 += BK) {
        for (int i = tid; i < BM * BK; i += 256) {
            int r = i / BK, c = i % BK;
            int gr = block_row + r;
            As[c][r] = (gr < N) ? A[(long)gr * K + k0 + c] : 0.f;
        }
        for (int i = tid; i < BK * BN; i += 256) {
            int r = i / BN, c = i % BN;
            Bs[r][c] = B[(long)(k0 + r) * M + block_col + c];
        }
        __syncthreads();

#pragma unroll
        for (int kk = 0; kk < BK; kk++) {
            float a[TM], b[TN];
#pragma unroll
            for (int i = 0; i < TM; i++) a[i] = As[kk][tr * TM + i];
#pragma unroll
            for (int j = 0; j < TN; j++) b[j] = Bs[kk][tc * TN + j];
#pragma unroll
            for (int i = 0; i < TM; i++)
#pragma unroll
                for (int j = 0; j < TN; j++) acc[i][j] += a[i] * b[j];
        }
        __syncthreads();
    }

#pragma unroll
    for (int i = 0; i < TM; i++) {
        int gr = block_row + tr * TM + i;
        if (gr < N) {
#pragma unroll
            for (int j = 0; j < TN; j++) {
                g_h1[(long)gr * M + block_col + tc * TN + j] = acc[i][j];
            }
        }
    }
}

// ---------------------------------------------------------------------------
// GEMM2: g_h2 = g_a1 @ W2  (K=256, M=16). One block = 16 rows, W in smem.
// ---------------------------------------------------------------------------
__global__ void gemm2_kernel(const float* __restrict__ W, int N) {
    const int K = H1, M = H2;
    __shared__ float Ws[K * M];        // 16 KB
    __shared__ float Asm[16][K];       // 16 KB

    int tx = threadIdx.x;  // 0..15  (col m)
    int ty = threadIdx.y;  // 0..15  (local row)
    int tid = ty * 16 + tx;

    for (int i = tid; i < K * M; i += 256) Ws[i] = W[i];

    int row0 = blockIdx.x * 16;
    for (int i = tid; i < 16 * K; i += 256) {
        int r = i / K, c = i % K;
        int gr = row0 + r;
        Asm[r][c] = (gr < N) ? g_a1[(long)gr * K + c] : 0.f;
    }
    __syncthreads();

    int n = row0 + ty;
    if (n >= N) return;

    float acc = 0.f;
#pragma unroll 8
    for (int k = 0; k < K; k++) acc += Asm[ty][k] * Ws[k * M + tx];
    g_h2[(long)n * M + tx] = acc;
}

// ---------------------------------------------------------------------------
// self-loop init kernels: out[i,f] = dinv[i]^2 * h[i,f]
// ---------------------------------------------------------------------------
__global__ void selfloop_h1_kernel(int N) {
    long idx = (long)blockIdx.x * blockDim.x + threadIdx.x;
    long total = (long)N * H1;
    if (idx < total) {
        int node = (int)(idx / H1);
        float v = g_dinv[node];
        g_a1[idx] = v * v * g_h1[idx];
    }
}
__global__ void selfloop_h2_kernel(int N) {
    long idx = (long)blockIdx.x * blockDim.x + threadIdx.x;
    long total = (long)N * H2;
    if (idx < total) {
        int node = (int)(idx / H2);
        float v = g_dinv[node];
        g_a2[idx] = v * v * g_h2[idx];
    }
}
__global__ void selfloop_a2_kernel(int N) {
    long idx = (long)blockIdx.x * blockDim.x + threadIdx.x;
    long total = (long)N * H2;
    if (idx < total) {
        int node = (int)(idx / H2);
        float v = g_dinv[node];
        g_a3[idx] = v * v * g_a2[idx];
    }
}

// ---------------------------------------------------------------------------
// edge scatters
// ---------------------------------------------------------------------------
__global__ void scatter1_kernel(const int* __restrict__ ei, int E, int N) {
    int warp = (int)((blockIdx.x * (long)blockDim.x + threadIdx.x) >> 5);
    int lane = threadIdx.x & 31;
    if (warp >= E) return;
    int s = ei[warp];
    int d = ei[E + warp];
    if ((unsigned)s >= (unsigned)N || (unsigned)d >= (unsigned)N) return;
    float norm = g_dinv[s] * g_dinv[d];
    const float* hs = g_h1 + (long)s * H1;
    float* od = g_a1 + (long)d * H1;
#pragma unroll
    for (int i = 0; i < 8; i++) {
        int f = i * 32 + lane;
        atomicAdd(&od[f], __ldg(&hs[f]) * norm);
    }
}

__global__ void scatter2_kernel(const int* __restrict__ ei, int E, int N) {
    long gid = (long)blockIdx.x * blockDim.x + threadIdx.x;
    int e = (int)(gid >> 4);
    int f = (int)(gid & 15);
    if (e >= E) return;
    int s = ei[e];
    int d = ei[E + e];
    if ((unsigned)s >= (unsigned)N || (unsigned)d >= (unsigned)N) return;
    float norm = g_dinv[s] * g_dinv[d];
    atomicAdd(&g_a2[(long)d * H2 + f], __ldg(&g_h2[(long)s * H2 + f]) * norm);
}

__global__ void scatter3_kernel(const int* __restrict__ ei, int E, int N) {
    long gid = (long)blockIdx.x * blockDim.x + threadIdx.x;
    int e = (int)(gid >> 4);
    int f = (int)(gid & 15);
    if (e >= E) return;
    int s = ei[e];
    int d = ei[E + e];
    if ((unsigned)s >= (unsigned)N || (unsigned)d >= (unsigned)N) return;
    float norm = g_dinv[s] * g_dinv[d];
    atomicAdd(&g_a3[(long)d * H2 + f], __ldg(&g_a2[(long)s * H2 + f]) * norm);
}

// ---------------------------------------------------------------------------
// bias + relu, in place
// ---------------------------------------------------------------------------
__global__ void bias_relu1_kernel(const float* __restrict__ b, int N) {
    long idx = (long)blockIdx.x * blockDim.x + threadIdx.x;
    long total = (long)N * H1;
    if (idx < total) {
        int f = (int)(idx % H1);
        float v = g_a1[idx] + b[f];
        g_a1[idx] = v > 0.f ? v : 0.f;
    }
}
__global__ void bias_relu2_kernel(const float* __restrict__ b, int N) {
    long idx = (long)blockIdx.x * blockDim.x + threadIdx.x;
    long total = (long)N * H2;
    if (idx < total) {
        int f = (int)(idx % H2);
        float v = g_a2[idx] + b[f];
        g_a2[idx] = v > 0.f ? v : 0.f;
    }
}

// ---------------------------------------------------------------------------
// final: o = g_a3 @ W3 + b3 ; log_softmax ; one thread per node
// ---------------------------------------------------------------------------
__global__ void final_kernel(const float* __restrict__ W3,
                             const float* __restrict__ b3,
                             float* __restrict__ out, int N) {
    __shared__ float Ws[H2 * F_OUT];   // 640 floats
    __shared__ float bs[F_OUT];
    int tid = threadIdx.x;
    for (int i = tid; i < H2 * F_OUT; i += blockDim.x) Ws[i] = W3[i];
    if (tid < F_OUT) bs[tid] = b3[tid];
    __syncthreads();

    int n = blockIdx.x * blockDim.x + tid;
    if (n >= N) return;

    float a[H2];
    const float4* ap = (const float4*)(g_a3 + (long)n * H2);
#pragma unroll
    for (int i = 0; i < 4; i++) {
        float4 v = ap[i];
        a[i * 4 + 0] = v.x; a[i * 4 + 1] = v.y;
        a[i * 4 + 2] = v.z; a[i * 4 + 3] = v.w;
    }

    float o[F_OUT];
#pragma unroll
    for (int m = 0; m < F_OUT; m++) {
        float acc = bs[m];
#pragma unroll
        for (int k = 0; k < H2; k++) acc += a[k] * Ws[k * F_OUT + m];
        o[m] = acc;
    }

    float mx = o[0];
#pragma unroll
    for (int m = 1; m < F_OUT; m++) mx = fmaxf(mx, o[m]);
    float sum = 0.f;
#pragma unroll
    for (int m = 0; m < F_OUT; m++) sum += __expf(o[m] - mx);
    float lse = mx + __logf(sum);

    float* op = out + (long)n * F_OUT;
#pragma unroll
    for (int m = 0; m < F_OUT; m++) op[m] = o[m] - lse;
}

// ---------------------------------------------------------------------------
// host launcher — launches only, no other runtime API calls
// ---------------------------------------------------------------------------
extern "C" void kernel_launch(void* const* d_in, const int* in_sizes, int n_in,
                              void* d_out, int out_size) {
    const float* x  = (const float*)d_in[0];
    const int*   ei = (const int*)d_in[1];      // int64 inputs arrive as int32
    const float* W1 = (const float*)d_in[2];
    const float* b1 = (const float*)d_in[3];
    const float* W2 = (const float*)d_in[4];
    const float* b2 = (const float*)d_in[5];
    const float* W3 = (const float*)d_in[6];
    const float* b3 = (const float*)d_in[7];
    float* out = (float*)d_out;

    int N = in_sizes[0] / F_IN;
    int E = in_sizes[1] / 2;

    // degrees + dinv
    zero_deg_kernel<<<(N + 255) / 256, 256>>>(N);
    count_deg_kernel<<<(E + 255) / 256, 256>>>(ei, E, N);
    dinv_kernel<<<(N + 255) / 256, 256>>>(N);

    // --- layer 1: h1 = x @ W1 ; a1 = Ahat h1 ; relu(a1 + b1) ---
    {
        dim3 grid(H1 / BN, (N + BM - 1) / BM);
        gemm1_kernel<<<grid, 256>>>(x, W1, N);
    }
    {
        long total = (long)N * H1;
        selfloop_h1_kernel<<<(int)((total + 255) / 256), 256>>>(N);
        long threads = (long)E * 32;
        scatter1_kernel<<<(int)((threads + 255) / 256), 256>>>(ei, E, N);
        bias_relu1_kernel<<<(int)((total + 255) / 256), 256>>>(b1, N);
    }

    // --- layer 2: h2 = r1 @ W2 ; a2 = Ahat h2 ; relu(a2 + b2) ---
    gemm2_kernel<<<(N + 15) / 16, dim3(16, 16)>>>(W2, N);
    {
        long total = (long)N * H2;
        selfloop_h2_kernel<<<(int)((total + 255) / 256), 256>>>(N);
        long threads = (long)E * 16;
        scatter2_kernel<<<(int)((threads + 255) / 256), 256>>>(ei, E, N);
        bias_relu2_kernel<<<(int)((total + 255) / 256), 256>>>(b2, N);
    }

    // --- layer 3 (aggregate-first): a3 = Ahat r2 ; out = a3 @ W3 + b3 ; log_softmax ---
    {
        long total = (long)N * H2;
        selfloop_a2_kernel<<<(int)((total + 255) / 256), 256>>>(N);
        long threads = (long)E * 16;
        scatter3_kernel<<<(int)((threads + 255) / 256), 256>>>(ei, E, N);
    }
    final_kernel<<<(N + 255) / 256, 256>>>(W3, b3, out, N);
}

// round 5
// speedup vs baseline: 1.4407x; 1.4407x over previous
#include <cuda_runtime.h>
#include <math.h>

// Problem constants (fixed for this problem instance)
#define NMAX   50000
#define EMAX   800000
#define F_IN   512
#define H1     256
#define H2     16
#define F_OUT  40

#define SCAN_B 256
#define NBLK   ((NMAX + SCAN_B - 1) / SCAN_B)   // 196

// Scratch (static device arrays; no allocation allowed)
__device__ float g_p1[NMAX * H1];   // dinv ⊙ (x @ W1)
__device__ float g_a1[NMAX * H1];   // relu(Ahat h1 + b1)
__device__ float g_p2[NMAX * H2];   // dinv ⊙ (a1 @ W2)
__device__ float g_p3[NMAX * H2];   // dinv ⊙ relu(Ahat h2 + b2)
__device__ float g_a3[NMAX * H2];   // Ahat r2
__device__ int   g_deg[NMAX];       // edge-only in-degree (no self loop)
__device__ int   g_rowstart[NMAX];
__device__ int   g_cursor[NMAX];
__device__ int   g_csrc[EMAX];      // src indices grouped by dst (CSR)
__device__ int   g_bsum[SCAN_B];    // block sums for scan (NBLK<=256)
__device__ float g_dinv[NMAX];

// ---------------------------------------------------------------------------
// degree / scan / CSR fill / dinv
// ---------------------------------------------------------------------------
__global__ void zero_deg_kernel(int N) {
    int i = blockIdx.x * blockDim.x + threadIdx.x;
    if (i < N) g_deg[i] = 0;
}

__global__ void count_deg_kernel(const int* __restrict__ ei, int E, int N) {
    int e = blockIdx.x * blockDim.x + threadIdx.x;
    if (e < E) {
        int d = ei[E + e];
        if ((unsigned)d < (unsigned)N) atomicAdd(&g_deg[d], 1);
    }
}

// block-wise exclusive scan of g_deg -> g_rowstart (partial), block totals -> g_bsum
__global__ void scan_partial_kernel(int N) {
    __shared__ int sd[SCAN_B];
    int t = threadIdx.x, b = blockIdx.x;
    int i = b * SCAN_B + t;
    int v = (i < N) ? g_deg[i] : 0;
    sd[t] = v;
    __syncthreads();
#pragma unroll
    for (int off = 1; off < SCAN_B; off <<= 1) {
        int x = (t >= off) ? sd[t - off] : 0;
        __syncthreads();
        sd[t] += x;
        __syncthreads();
    }
    if (i < N) g_rowstart[i] = sd[t] - v;       // exclusive
    if (t == SCAN_B - 1) g_bsum[b] = sd[t];     // block total
}

__global__ void scan_bsum_kernel(int nblk) {
    __shared__ int sd[SCAN_B];
    int t = threadIdx.x;
    int v = (t < nblk) ? g_bsum[t] : 0;
    sd[t] = v;
    __syncthreads();
#pragma unroll
    for (int off = 1; off < SCAN_B; off <<= 1) {
        int x = (t >= off) ? sd[t - off] : 0;
        __syncthreads();
        sd[t] += x;
        __syncthreads();
    }
    if (t < nblk) g_bsum[t] = sd[t] - v;        // exclusive
}

__global__ void scan_add_kernel(int N) {
    int i = blockIdx.x * blockDim.x + threadIdx.x;
    if (i < N) {
        int r = g_rowstart[i] + g_bsum[i / SCAN_B];
        g_rowstart[i] = r;
        g_cursor[i] = r;
    }
}

__global__ void csr_fill_kernel(const int* __restrict__ ei, int E, int N) {
    int e = blockIdx.x * blockDim.x + threadIdx.x;
    if (e < E) {
        int s = ei[e];
        int d = ei[E + e];
        if ((unsigned)s < (unsigned)N && (unsigned)d < (unsigned)N) {
            int pos = atomicAdd(&g_cursor[d], 1);
            g_csrc[pos] = s;
        }
    }
}

__global__ void dinv_kernel(int N) {
    int i = blockIdx.x * blockDim.x + threadIdx.x;
    if (i < N) g_dinv[i] = rsqrtf((float)(g_deg[i] + 1));  // +1 self-loop
}

// ---------------------------------------------------------------------------
// GEMM1: g_p1[N,256] = dinv ⊙ (A[N,512] @ B[512,256])
// 128x128x8 tiles, 8x8 per-thread, double-buffered smem, float4 everywhere
// ---------------------------------------------------------------------------
#define G1_BM 128
#define G1_BN 128
#define G1_BK 8

__global__ void __launch_bounds__(256) gemm1_kernel(const float* __restrict__ A,
                                                    const float* __restrict__ B,
                                                    int N) {
    const int K = F_IN, M = H1;
    __shared__ float As[2][G1_BK][G1_BM + 4];   // [k][m], row stride 132 (16B-aligned)
    __shared__ float Bs[2][G1_BK][G1_BN];

    int tid = threadIdx.x;
    int brow = blockIdx.y * G1_BM;
    int bcol = blockIdx.x * G1_BN;

    // A-load mapping: 128 rows x 8 cols = 1024 floats / 256 thr = 1 float4
    int arow = tid >> 1;
    int acol = (tid & 1) * 4;
    // B-load mapping: 8 rows x 128 cols
    int brk = tid >> 5;
    int bcg = (tid & 31) * 4;
    // compute mapping: 16x16 thread grid of 8x8 tiles
    int tr = tid / 16;
    int tc = tid % 16;

    float acc[8][8];
#pragma unroll
    for (int i = 0; i < 8; i++)
#pragma unroll
        for (int j = 0; j < 8; j++) acc[i][j] = 0.f;

    float4 aReg, bReg;
    // preload tile 0
    {
        int gr = brow + arow;
        aReg = (gr < N) ? *(const float4*)&A[(long)gr * K + acol]
                        : make_float4(0.f, 0.f, 0.f, 0.f);
        bReg = *(const float4*)&B[(long)brk * M + bcol + bcg];
    }
    As[0][acol + 0][arow] = aReg.x;
    As[0][acol + 1][arow] = aReg.y;
    As[0][acol + 2][arow] = aReg.z;
    As[0][acol + 3][arow] = aReg.w;
    *(float4*)&Bs[0][brk][bcg] = bReg;
    __syncthreads();

    int buf = 0;
    for (int k0 = 0; k0 < K; k0 += G1_BK) {
        int knext = k0 + G1_BK;
        if (knext < K) {
            int gr = brow + arow;
            aReg = (gr < N) ? *(const float4*)&A[(long)gr * K + knext + acol]
                            : make_float4(0.f, 0.f, 0.f, 0.f);
            bReg = *(const float4*)&B[(long)(knext + brk) * M + bcol + bcg];
        }
#pragma unroll
        for (int kk = 0; kk < G1_BK; kk++) {
            float a[8], b[8];
            *(float4*)&a[0] = *(const float4*)&As[buf][kk][tr * 8];
            *(float4*)&a[4] = *(const float4*)&As[buf][kk][tr * 8 + 4];
            *(float4*)&b[0] = *(const float4*)&Bs[buf][kk][tc * 8];
            *(float4*)&b[4] = *(const float4*)&Bs[buf][kk][tc * 8 + 4];
#pragma unroll
            for (int i = 0; i < 8; i++)
#pragma unroll
                for (int j = 0; j < 8; j++) acc[i][j] += a[i] * b[j];
        }
        if (knext < K) {
            int nb = buf ^ 1;
            As[nb][acol + 0][arow] = aReg.x;
            As[nb][acol + 1][arow] = aReg.y;
            As[nb][acol + 2][arow] = aReg.z;
            As[nb][acol + 3][arow] = aReg.w;
            *(float4*)&Bs[nb][brk][bcg] = bReg;
            __syncthreads();
            buf = nb;
        }
    }

    // epilogue: scale by dinv[row], write p1
#pragma unroll
    for (int i = 0; i < 8; i++) {
        int gr = brow + tr * 8 + i;
        if (gr < N) {
            float dv = g_dinv[gr];
            float4 v0 = make_float4(dv * acc[i][0], dv * acc[i][1],
                                    dv * acc[i][2], dv * acc[i][3]);
            float4 v1 = make_float4(dv * acc[i][4], dv * acc[i][5],
                                    dv * acc[i][6], dv * acc[i][7]);
            float* op = &g_p1[(long)gr * M + bcol + tc * 8];
            *(float4*)&op[0] = v0;
            *(float4*)&op[4] = v1;
        }
    }
}

// ---------------------------------------------------------------------------
// gather1 (F=256): a1[d] = relu(dinv[d]*(p1[d] + sum_nbr p1[s]) + b1)
// one block (256 threads) per dst node; neighbor idx staged in smem
// ---------------------------------------------------------------------------
__global__ void __launch_bounds__(256) gather1_kernel(const float* __restrict__ b1, int N) {
    __shared__ int nbr[256];
    int d = blockIdx.x;
    if (d >= N) return;
    int f = threadIdx.x;

    int start = g_rowstart[d];
    int deg = g_deg[d];

    float acc = g_p1[(long)d * H1 + f];   // self loop (p1 already dinv-scaled)
    for (int base = 0; base < deg; base += 256) {
        int cnt = min(256, deg - base);
        if (f < cnt) nbr[f] = g_csrc[start + base + f];
        __syncthreads();
        for (int j = 0; j < cnt; j++) {
            acc += g_p1[(long)nbr[j] * H1 + f];
        }
        __syncthreads();
    }
    float v = g_dinv[d] * acc + b1[f];
    g_a1[(long)d * H1 + f] = v > 0.f ? v : 0.f;
}

// ---------------------------------------------------------------------------
// GEMM2: g_p2 = dinv ⊙ (a1 @ W2)   (K=256, M=16)
// ---------------------------------------------------------------------------
__global__ void gemm2_kernel(const float* __restrict__ W, int N) {
    const int K = H1, M = H2;
    __shared__ float Ws[K * M];        // 16 KB
    __shared__ float Asm[16][K];       // 16 KB

    int tx = threadIdx.x;  // 0..15  (col m)
    int ty = threadIdx.y;  // 0..15  (local row)
    int tid = ty * 16 + tx;

    for (int i = tid; i < K * M; i += 256) Ws[i] = W[i];

    int row0 = blockIdx.x * 16;
    for (int i = tid; i < 16 * K; i += 256) {
        int r = i / K, c = i % K;
        int gr = row0 + r;
        Asm[r][c] = (gr < N) ? g_a1[(long)gr * K + c] : 0.f;
    }
    __syncthreads();

    int n = row0 + ty;
    if (n >= N) return;

    float acc = 0.f;
#pragma unroll 8
    for (int k = 0; k < K; k++) acc += Asm[ty][k] * Ws[k * M + tx];
    g_p2[(long)n * M + tx] = g_dinv[n] * acc;
}

// ---------------------------------------------------------------------------
// gather2 (F=16): p3[d] = dinv[d] * relu(dinv[d]*(p2[d]+sum p2[s]) + b2)
// 16 threads per node, 16 nodes per block
// ---------------------------------------------------------------------------
__global__ void __launch_bounds__(256) gather2_kernel(const float* __restrict__ b2, int N) {
    int t = threadIdx.x;
    int d = blockIdx.x * 16 + (t >> 4);
    int f = t & 15;
    if (d >= N) return;

    int start = g_rowstart[d];
    int deg = g_deg[d];
    float acc = g_p2[(long)d * H2 + f];
    for (int j = 0; j < deg; j++) {
        int s = g_csrc[start + j];
        acc += g_p2[(long)s * H2 + f];
    }
    float dv = g_dinv[d];
    float v = dv * acc + b2[f];
    g_p3[(long)d * H2 + f] = dv * (v > 0.f ? v : 0.f);
}

// ---------------------------------------------------------------------------
// gather3 (F=16): a3[d] = dinv[d]*(p3[d]+sum p3[s])
// ---------------------------------------------------------------------------
__global__ void __launch_bounds__(256) gather3_kernel(int N) {
    int t = threadIdx.x;
    int d = blockIdx.x * 16 + (t >> 4);
    int f = t & 15;
    if (d >= N) return;

    int start = g_rowstart[d];
    int deg = g_deg[d];
    float acc = g_p3[(long)d * H2 + f];
    for (int j = 0; j < deg; j++) {
        int s = g_csrc[start + j];
        acc += g_p3[(long)s * H2 + f];
    }
    g_a3[(long)d * H2 + f] = g_dinv[d] * acc;
}

// ---------------------------------------------------------------------------
// final: o = g_a3 @ W3 + b3 ; log_softmax ; one thread per node
// ---------------------------------------------------------------------------
__global__ void final_kernel(const float* __restrict__ W3,
                             const float* __restrict__ b3,
                             float* __restrict__ out, int N) {
    __shared__ float Ws[H2 * F_OUT];
    __shared__ float bs[F_OUT];
    int tid = threadIdx.x;
    for (int i = tid; i < H2 * F_OUT; i += blockDim.x) Ws[i] = W3[i];
    if (tid < F_OUT) bs[tid] = b3[tid];
    __syncthreads();

    int n = blockIdx.x * blockDim.x + tid;
    if (n >= N) return;

    float a[H2];
    const float4* ap = (const float4*)(g_a3 + (long)n * H2);
#pragma unroll
    for (int i = 0; i < 4; i++) {
        float4 v = ap[i];
        a[i * 4 + 0] = v.x; a[i * 4 + 1] = v.y;
        a[i * 4 + 2] = v.z; a[i * 4 + 3] = v.w;
    }

    float o[F_OUT];
#pragma unroll
    for (int m = 0; m < F_OUT; m++) {
        float acc = bs[m];
#pragma unroll
        for (int k = 0; k < H2; k++) acc += a[k] * Ws[k * F_OUT + m];
        o[m] = acc;
    }

    float mx = o[0];
#pragma unroll
    for (int m = 1; m < F_OUT; m++) mx = fmaxf(mx, o[m]);
    float sum = 0.f;
#pragma unroll
    for (int m = 0; m < F_OUT; m++) sum += __expf(o[m] - mx);
    float lse = mx + __logf(sum);

    float* op = out + (long)n * F_OUT;
#pragma unroll
    for (int m = 0; m < F_OUT; m++) op[m] = o[m] - lse;
}

// ---------------------------------------------------------------------------
// host launcher — kernel launches only
// ---------------------------------------------------------------------------
extern "C" void kernel_launch(void* const* d_in, const int* in_sizes, int n_in,
                              void* d_out, int out_size) {
    const float* x  = (const float*)d_in[0];
    const int*   ei = (const int*)d_in[1];      // int64 delivered as int32
    const float* W1 = (const float*)d_in[2];
    const float* b1 = (const float*)d_in[3];
    const float* W2 = (const float*)d_in[4];
    const float* b2 = (const float*)d_in[5];
    const float* W3 = (const float*)d_in[6];
    const float* b3 = (const float*)d_in[7];
    float* out = (float*)d_out;

    int N = in_sizes[0] / F_IN;
    int E = in_sizes[1] / 2;
    int nblk = (N + SCAN_B - 1) / SCAN_B;

    // degrees -> CSR -> dinv
    zero_deg_kernel<<<(N + 255) / 256, 256>>>(N);
    count_deg_kernel<<<(E + 255) / 256, 256>>>(ei, E, N);
    scan_partial_kernel<<<nblk, SCAN_B>>>(N);
    scan_bsum_kernel<<<1, SCAN_B>>>(nblk);
    scan_add_kernel<<<(N + 255) / 256, 256>>>(N);
    csr_fill_kernel<<<(E + 255) / 256, 256>>>(ei, E, N);
    dinv_kernel<<<(N + 255) / 256, 256>>>(N);

    // layer 1
    {
        dim3 grid(H1 / G1_BN, (N + G1_BM - 1) / G1_BM);
        gemm1_kernel<<<grid, 256>>>(x, W1, N);
    }
    gather1_kernel<<<N, 256>>>(b1, N);

    // layer 2
    gemm2_kernel<<<(N + 15) / 16, dim3(16, 16)>>>(W2, N);
    gather2_kernel<<<(N + 15) / 16, 256>>>(b2, N);

    // layer 3 (aggregate-first) + head
    gather3_kernel<<<(N + 15) / 16, 256>>>(N);
    final_kernel<<<(N + 255) / 256, 256>>>(W3, b3, out, N);
}

// round 6
// speedup vs baseline: 2.1112x; 1.4654x over previous
#include <cuda_runtime.h>
#include <math.h>
#include <stdint.h>

// Problem constants (fixed for this problem instance)
#define NMAX   50000
#define EMAX   800000
#define F_IN   512
#define H1     256
#define H2     16
#define F_OUT  40

#define SCAN_B 256

// Scratch (static device arrays; no allocation allowed)
__device__ float g_p1[NMAX * H1];   // dinv ⊙ (x @ W1)
__device__ float g_a1[NMAX * H1];   // relu(Ahat h1 + b1)
__device__ float g_p2[NMAX * H2];   // dinv ⊙ (a1 @ W2)
__device__ float g_p3[NMAX * H2];   // dinv ⊙ relu(Ahat h2 + b2)
__device__ float g_a3[NMAX * H2];   // Ahat r2
__device__ int   g_deg[NMAX];       // edge-only in-degree (no self loop)
__device__ int   g_rowstart[NMAX];
__device__ int   g_cursor[NMAX];
__device__ int   g_csrc[EMAX];      // src indices grouped by dst (CSR)
__device__ int   g_bsum[SCAN_B];
__device__ float g_dinv[NMAX];

// ---------------------------------------------------------------------------
// degree / scan / CSR fill / dinv
// ---------------------------------------------------------------------------
__global__ void zero_deg_kernel(int N) {
    int i = blockIdx.x * blockDim.x + threadIdx.x;
    if (i < N) g_deg[i] = 0;
}

__global__ void count_deg_kernel(const int* __restrict__ ei, int E, int N) {
    int e = blockIdx.x * blockDim.x + threadIdx.x;
    if (e < E) {
        int d = ei[E + e];
        if ((unsigned)d < (unsigned)N) atomicAdd(&g_deg[d], 1);
    }
}

__global__ void scan_partial_kernel(int N) {
    __shared__ int sd[SCAN_B];
    int t = threadIdx.x, b = blockIdx.x;
    int i = b * SCAN_B + t;
    int v = (i < N) ? g_deg[i] : 0;
    sd[t] = v;
    __syncthreads();
#pragma unroll
    for (int off = 1; off < SCAN_B; off <<= 1) {
        int x = (t >= off) ? sd[t - off] : 0;
        __syncthreads();
        sd[t] += x;
        __syncthreads();
    }
    if (i < N) g_rowstart[i] = sd[t] - v;       // exclusive
    if (t == SCAN_B - 1) g_bsum[b] = sd[t];
}

__global__ void scan_bsum_kernel(int nblk) {
    __shared__ int sd[SCAN_B];
    int t = threadIdx.x;
    int v = (t < nblk) ? g_bsum[t] : 0;
    sd[t] = v;
    __syncthreads();
#pragma unroll
    for (int off = 1; off < SCAN_B; off <<= 1) {
        int x = (t >= off) ? sd[t - off] : 0;
        __syncthreads();
        sd[t] += x;
        __syncthreads();
    }
    if (t < nblk) g_bsum[t] = sd[t] - v;
}

__global__ void scan_add_kernel(int N) {
    int i = blockIdx.x * blockDim.x + threadIdx.x;
    if (i < N) {
        int r = g_rowstart[i] + g_bsum[i / SCAN_B];
        g_rowstart[i] = r;
        g_cursor[i] = r;
    }
}

__global__ void csr_fill_kernel(const int* __restrict__ ei, int E, int N) {
    int e = blockIdx.x * blockDim.x + threadIdx.x;
    if (e < E) {
        int s = ei[e];
        int d = ei[E + e];
        if ((unsigned)s < (unsigned)N && (unsigned)d < (unsigned)N) {
            int pos = atomicAdd(&g_cursor[d], 1);
            g_csrc[pos] = s;
        }
    }
}

__global__ void dinv_kernel(int N) {
    int i = blockIdx.x * blockDim.x + threadIdx.x;
    if (i < N) g_dinv[i] = rsqrtf((float)(g_deg[i] + 1));  // +1 self-loop
}

// ---------------------------------------------------------------------------
// GEMM1 (tf32 tensor cores): g_p1[N,256] = dinv ⊙ (A[N,512] @ B[512,256])
// block 128x128x16, 8 warps, warp tile 64x32 via mma.m16n8k8.tf32
// ---------------------------------------------------------------------------
#define G1_BM 128
#define G1_BN 128
#define G1_BK 16
#define AS_STRIDE 20    // conflict-free for A-fragment LDS pattern
#define BS_STRIDE 132   // conflict-free for B-fragment LDS pattern

__device__ __forceinline__ uint32_t f2tf32(float x) {
    uint32_t r;
    asm("cvt.rna.tf32.f32 %0, %1;" : "=r"(r) : "f"(x));
    return r;
}

__device__ __forceinline__ void mma_tf32(float c[4], const uint32_t a[4],
                                         const uint32_t b[2]) {
    asm volatile(
        "mma.sync.aligned.m16n8k8.row.col.f32.tf32.tf32.f32 "
        "{%0,%1,%2,%3}, {%4,%5,%6,%7}, {%8,%9}, {%0,%1,%2,%3};"
        : "+f"(c[0]), "+f"(c[1]), "+f"(c[2]), "+f"(c[3])
        : "r"(a[0]), "r"(a[1]), "r"(a[2]), "r"(a[3]), "r"(b[0]), "r"(b[1]));
}

__global__ void __launch_bounds__(256) gemm1_kernel(const float* __restrict__ A,
                                                    const float* __restrict__ B,
                                                    int N) {
    const int K = F_IN, M = H1;
    __shared__ uint32_t As[2][G1_BM * AS_STRIDE];   // 2*128*20*4 = 20 KB
    __shared__ uint32_t Bs[2][G1_BK * BS_STRIDE];   // 2*16*132*4 = 16.5 KB

    int tid = threadIdx.x;
    int lane = tid & 31;
    int w = tid >> 5;
    int wm = w >> 2;          // 0..1
    int wn = w & 3;           // 0..3
    int brow = blockIdx.y * G1_BM;
    int bcol = blockIdx.x * G1_BN;

    // global-load mapping
    int arow = tid >> 1;               // 0..127
    int acg  = (tid & 1) * 4;          // col offset 0 or 4 (and +8)
    int bk   = tid >> 4;               // 0..15
    int bn   = (tid & 15) * 4;         // 0..60 (and +64)

    float acc[4][4][4];
#pragma unroll
    for (int mi = 0; mi < 4; mi++)
#pragma unroll
        for (int ni = 0; ni < 4; ni++)
#pragma unroll
            for (int q = 0; q < 4; q++) acc[mi][ni][q] = 0.f;

    float4 a4a, a4b, b4a, b4b;
    // preload tile 0
    {
        int gr = brow + arow;
        if (gr < N) {
            a4a = *(const float4*)&A[(long)gr * K + acg];
            a4b = *(const float4*)&A[(long)gr * K + acg + 8];
        } else {
            a4a = make_float4(0.f, 0.f, 0.f, 0.f);
            a4b = a4a;
        }
        b4a = *(const float4*)&B[(long)bk * M + bcol + bn];
        b4b = *(const float4*)&B[(long)bk * M + bcol + bn + 64];
    }
    {
        uint32_t* ap = &As[0][arow * AS_STRIDE + acg];
        ap[0] = f2tf32(a4a.x); ap[1] = f2tf32(a4a.y);
        ap[2] = f2tf32(a4a.z); ap[3] = f2tf32(a4a.w);
        ap[8] = f2tf32(a4b.x); ap[9] = f2tf32(a4b.y);
        ap[10] = f2tf32(a4b.z); ap[11] = f2tf32(a4b.w);
        uint32_t* bp = &Bs[0][bk * BS_STRIDE + bn];
        bp[0] = f2tf32(b4a.x); bp[1] = f2tf32(b4a.y);
        bp[2] = f2tf32(b4a.z); bp[3] = f2tf32(b4a.w);
        bp[64] = f2tf32(b4b.x); bp[65] = f2tf32(b4b.y);
        bp[66] = f2tf32(b4b.z); bp[67] = f2tf32(b4b.w);
    }
    __syncthreads();

    int buf = 0;
    for (int k0 = 0; k0 < K; k0 += G1_BK) {
        int knext = k0 + G1_BK;
        if (knext < K) {
            int gr = brow + arow;
            if (gr < N) {
                a4a = *(const float4*)&A[(long)gr * K + knext + acg];
                a4b = *(const float4*)&A[(long)gr * K + knext + acg + 8];
            } else {
                a4a = make_float4(0.f, 0.f, 0.f, 0.f);
                a4b = a4a;
            }
            b4a = *(const float4*)&B[(long)(knext + bk) * M + bcol + bn];
            b4b = *(const float4*)&B[(long)(knext + bk) * M + bcol + bn + 64];
        }

        // compute over current buffer: 2 k-steps of 8
#pragma unroll
        for (int ks = 0; ks < 2; ks++) {
            int kk = ks * 8;
            uint32_t af[4][4], bf[4][2];
#pragma unroll
            for (int mi = 0; mi < 4; mi++) {
                int r = wm * 64 + mi * 16 + (lane >> 2);
                int c = kk + (lane & 3);
                af[mi][0] = As[buf][r * AS_STRIDE + c];
                af[mi][1] = As[buf][(r + 8) * AS_STRIDE + c];
                af[mi][2] = As[buf][r * AS_STRIDE + c + 4];
                af[mi][3] = As[buf][(r + 8) * AS_STRIDE + c + 4];
            }
#pragma unroll
            for (int ni = 0; ni < 4; ni++) {
                int c = wn * 32 + ni * 8 + (lane >> 2);
                int k1 = kk + (lane & 3);
                bf[ni][0] = Bs[buf][k1 * BS_STRIDE + c];
                bf[ni][1] = Bs[buf][(k1 + 4) * BS_STRIDE + c];
            }
#pragma unroll
            for (int mi = 0; mi < 4; mi++)
#pragma unroll
                for (int ni = 0; ni < 4; ni++)
                    mma_tf32(acc[mi][ni], af[mi], bf[ni]);
        }

        if (knext < K) {
            int nb = buf ^ 1;
            uint32_t* ap = &As[nb][arow * AS_STRIDE + acg];
            ap[0] = f2tf32(a4a.x); ap[1] = f2tf32(a4a.y);
            ap[2] = f2tf32(a4a.z); ap[3] = f2tf32(a4a.w);
            ap[8] = f2tf32(a4b.x); ap[9] = f2tf32(a4b.y);
            ap[10] = f2tf32(a4b.z); ap[11] = f2tf32(a4b.w);
            uint32_t* bp = &Bs[nb][bk * BS_STRIDE + bn];
            bp[0] = f2tf32(b4a.x); bp[1] = f2tf32(b4a.y);
            bp[2] = f2tf32(b4a.z); bp[3] = f2tf32(b4a.w);
            bp[64] = f2tf32(b4b.x); bp[65] = f2tf32(b4b.y);
            bp[66] = f2tf32(b4b.z); bp[67] = f2tf32(b4b.w);
            __syncthreads();
            buf = nb;
        }
    }

    // epilogue: scale by dinv[row], write p1 (float2 per fragment row)
#pragma unroll
    for (int mi = 0; mi < 4; mi++) {
        int r0 = brow + wm * 64 + mi * 16 + (lane >> 2);
        int r1 = r0 + 8;
        float dv0 = (r0 < N) ? g_dinv[r0] : 0.f;
        float dv1 = (r1 < N) ? g_dinv[r1] : 0.f;
#pragma unroll
        for (int ni = 0; ni < 4; ni++) {
            int c = bcol + wn * 32 + ni * 8 + (lane & 3) * 2;
            if (r0 < N) {
                float2 v = make_float2(dv0 * acc[mi][ni][0], dv0 * acc[mi][ni][1]);
                *(float2*)&g_p1[(long)r0 * M + c] = v;
            }
            if (r1 < N) {
                float2 v = make_float2(dv1 * acc[mi][ni][2], dv1 * acc[mi][ni][3]);
                *(float2*)&g_p1[(long)r1 * M + c] = v;
            }
        }
    }
}

// ---------------------------------------------------------------------------
// gather1 (F=256): a1[d] = relu(dinv[d]*(p1[d] + sum_nbr p1[s]) + b1)
// ---------------------------------------------------------------------------
__global__ void __launch_bounds__(256) gather1_kernel(const float* __restrict__ b1, int N) {
    __shared__ int nbr[256];
    int d = blockIdx.x;
    if (d >= N) return;
    int f = threadIdx.x;

    int start = g_rowstart[d];
    int deg = g_deg[d];

    float acc = g_p1[(long)d * H1 + f];   // self loop (p1 already dinv-scaled)
    for (int base = 0; base < deg; base += 256) {
        int cnt = min(256, deg - base);
        if (f < cnt) nbr[f] = g_csrc[start + base + f];
        __syncthreads();
        for (int j = 0; j < cnt; j++) {
            acc += g_p1[(long)nbr[j] * H1 + f];
        }
        __syncthreads();
    }
    float v = g_dinv[d] * acc + b1[f];
    g_a1[(long)d * H1 + f] = v > 0.f ? v : 0.f;
}

// ---------------------------------------------------------------------------
// GEMM2: g_p2 = dinv ⊙ (a1 @ W2)   (K=256, M=16)
// ---------------------------------------------------------------------------
__global__ void gemm2_kernel(const float* __restrict__ W, int N) {
    const int K = H1, M = H2;
    __shared__ float Ws[K * M];        // 16 KB
    __shared__ float Asm[16][K];       // 16 KB

    int tx = threadIdx.x;  // 0..15  (col m)
    int ty = threadIdx.y;  // 0..15  (local row)
    int tid = ty * 16 + tx;

    for (int i = tid; i < K * M; i += 256) Ws[i] = W[i];

    int row0 = blockIdx.x * 16;
    for (int i = tid; i < 16 * K; i += 256) {
        int r = i / K, c = i % K;
        int gr = row0 + r;
        Asm[r][c] = (gr < N) ? g_a1[(long)gr * K + c] : 0.f;
    }
    __syncthreads();

    int n = row0 + ty;
    if (n >= N) return;

    float acc = 0.f;
#pragma unroll 8
    for (int k = 0; k < K; k++) acc += Asm[ty][k] * Ws[k * M + tx];
    g_p2[(long)n * M + tx] = g_dinv[n] * acc;
}

// ---------------------------------------------------------------------------
// gather2 (F=16): p3[d] = dinv[d] * relu(dinv[d]*(p2[d]+sum p2[s]) + b2)
// ---------------------------------------------------------------------------
__global__ void __launch_bounds__(256) gather2_kernel(const float* __restrict__ b2, int N) {
    int t = threadIdx.x;
    int d = blockIdx.x * 16 + (t >> 4);
    int f = t & 15;
    if (d >= N) return;

    int start = g_rowstart[d];
    int deg = g_deg[d];
    float acc = g_p2[(long)d * H2 + f];
    for (int j = 0; j < deg; j++) {
        int s = g_csrc[start + j];
        acc += g_p2[(long)s * H2 + f];
    }
    float dv = g_dinv[d];
    float v = dv * acc + b2[f];
    g_p3[(long)d * H2 + f] = dv * (v > 0.f ? v : 0.f);
}

// ---------------------------------------------------------------------------
// gather3 (F=16): a3[d] = dinv[d]*(p3[d]+sum p3[s])
// ---------------------------------------------------------------------------
__global__ void __launch_bounds__(256) gather3_kernel(int N) {
    int t = threadIdx.x;
    int d = blockIdx.x * 16 + (t >> 4);
    int f = t & 15;
    if (d >= N) return;

    int start = g_rowstart[d];
    int deg = g_deg[d];
    float acc = g_p3[(long)d * H2 + f];
    for (int j = 0; j < deg; j++) {
        int s = g_csrc[start + j];
        acc += g_p3[(long)s * H2 + f];
    }
    g_a3[(long)d * H2 + f] = g_dinv[d] * acc;
}

// ---------------------------------------------------------------------------
// final: o = g_a3 @ W3 + b3 ; log_softmax ; one thread per node
// ---------------------------------------------------------------------------
__global__ void final_kernel(const float* __restrict__ W3,
                             const float* __restrict__ b3,
                             float* __restrict__ out, int N) {
    __shared__ float Ws[H2 * F_OUT];
    __shared__ float bs[F_OUT];
    int tid = threadIdx.x;
    for (int i = tid; i < H2 * F_OUT; i += blockDim.x) Ws[i] = W3[i];
    if (tid < F_OUT) bs[tid] = b3[tid];
    __syncthreads();

    int n = blockIdx.x * blockDim.x + tid;
    if (n >= N) return;

    float a[H2];
    const float4* ap = (const float4*)(g_a3 + (long)n * H2);
#pragma unroll
    for (int i = 0; i < 4; i++) {
        float4 v = ap[i];
        a[i * 4 + 0] = v.x; a[i * 4 + 1] = v.y;
        a[i * 4 + 2] = v.z; a[i * 4 + 3] = v.w;
    }

    float o[F_OUT];
#pragma unroll
    for (int m = 0; m < F_OUT; m++) {
        float acc = bs[m];
#pragma unroll
        for (int k = 0; k < H2; k++) acc += a[k] * Ws[k * F_OUT + m];
        o[m] = acc;
    }

    float mx = o[0];
#pragma unroll
    for (int m = 1; m < F_OUT; m++) mx = fmaxf(mx, o[m]);
    float sum = 0.f;
#pragma unroll
    for (int m = 0; m < F_OUT; m++) sum += __expf(o[m] - mx);
    float lse = mx + __logf(sum);

    float* op = out + (long)n * F_OUT;
#pragma unroll
    for (int m = 0; m < F_OUT; m++) op[m] = o[m] - lse;
}

// ---------------------------------------------------------------------------
// host launcher — kernel launches only
// ---------------------------------------------------------------------------
extern "C" void kernel_launch(void* const* d_in, const int* in_sizes, int n_in,
                              void* d_out, int out_size) {
    const float* x  = (const float*)d_in[0];
    const int*   ei = (const int*)d_in[1];      // int64 delivered as int32
    const float* W1 = (const float*)d_in[2];
    const float* b1 = (const float*)d_in[3];
    const float* W2 = (const float*)d_in[4];
    const float* b2 = (const float*)d_in[5];
    const float* W3 = (const float*)d_in[6];
    const float* b3 = (const float*)d_in[7];
    float* out = (float*)d_out;

    int N = in_sizes[0] / F_IN;
    int E = in_sizes[1] / 2;
    int nblk = (N + SCAN_B - 1) / SCAN_B;

    // degrees -> CSR -> dinv
    zero_deg_kernel<<<(N + 255) / 256, 256>>>(N);
    count_deg_kernel<<<(E + 255) / 256, 256>>>(ei, E, N);
    scan_partial_kernel<<<nblk, SCAN_B>>>(N);
    scan_bsum_kernel<<<1, SCAN_B>>>(nblk);
    scan_add_kernel<<<(N + 255) / 256, 256>>>(N);
    csr_fill_kernel<<<(E + 255) / 256, 256>>>(ei, E, N);
    dinv_kernel<<<(N + 255) / 256, 256>>>(N);

    // layer 1 (tf32 tensor-core GEMM, dinv fused)
    {
        dim3 grid(H1 / G1_BN, (N + G1_BM - 1) / G1_BM);
        gemm1_kernel<<<grid, 256>>>(x, W1, N);
    }
    gather1_kernel<<<N, 256>>>(b1, N);

    // layer 2
    gemm2_kernel<<<(N + 15) / 16, dim3(16, 16)>>>(W2, N);
    gather2_kernel<<<(N + 15) / 16, 256>>>(b2, N);

    // layer 3 (aggregate-first) + head
    gather3_kernel<<<(N + 15) / 16, 256>>>(N);
    final_kernel<<<(N + 255) / 256, 256>>>(W3, b3, out, N);
}